// round 1
// baseline (speedup 1.0000x reference)
#include <cuda_runtime.h>
#include <cstdint>

#define NPG   64
#define IN_F  128
#define OUT_F 128

typedef unsigned long long u64;

#define FMA2(d, a, b) asm("fma.rn.f32x2 %0, %1, %2, %0;" : "+l"(d) : "l"(a), "l"(b))
#define PACK2(d, s)   asm("mov.b64 %0, {%1, %1};"        : "=l"(d) : "r"(s))
#define ADD2(d, a, b) asm("add.rn.f32x2 %0, %1, %2;"     : "=l"(d) : "l"(a), "l"(b))

__global__ void __launch_bounds__(256, 2)
mhl_kernel(const float* __restrict__ x,
           const int*   __restrict__ head,
           const float* __restrict__ kern,
           const float* __restrict__ bias,
           float*       __restrict__ out)
{
    extern __shared__ float smem[];
    float* Ws = smem;                 // [IN_F][OUT_F]  64 KB
    float* Xs = smem + IN_F * OUT_F;  // [NPG][IN_F]    32 KB

    const int g   = blockIdx.x;
    const int tid = threadIdx.x;
    const int h   = head[g];

    const float* W  = kern + (size_t)h * IN_F * OUT_F;
    const float* Xg = x    + (size_t)g * NPG * IN_F;

    // ---- load W tile: 16384 floats = 4096 float4, 16 per thread, coalesced
    {
        const float4* W4  = (const float4*)W;
        float4*       Ws4 = (float4*)Ws;
        #pragma unroll
        for (int i = 0; i < 16; i++)
            Ws4[tid + i * 256] = W4[tid + i * 256];
    }
    // ---- load X tile (natural [m][k] layout): 2048 float4, 8 per thread
    {
        const float4* X4  = (const float4*)Xg;
        float4*       Xs4 = (float4*)Xs;
        #pragma unroll
        for (int i = 0; i < 8; i++)
            Xs4[tid + i * 256] = X4[tid + i * 256];
    }
    __syncthreads();

    const int tn = tid & 15;      // 16 n-tiles of 8
    const int tm = tid >> 4;      // 16 m-tiles of 4
    const int n0 = tn * 8;
    const int m0 = tm * 4;

    // accumulators: 4 m-rows x 4 n-pairs (n0+2p, n0+2p+1), packed f32x2
    u64 acc[4][4];
    #pragma unroll
    for (int i = 0; i < 4; i++)
        #pragma unroll
        for (int p = 0; p < 4; p++)
            acc[i][p] = 0ull;

    #pragma unroll 8
    for (int k4 = 0; k4 < IN_F / 4; k4++) {
        // x fragments: 4 m-rows, 4 k each (vectorized along k)
        float xr[4][4];
        #pragma unroll
        for (int i = 0; i < 4; i++) {
            float4 v = *(const float4*)&Xs[(m0 + i) * IN_F + k4 * 4];
            xr[i][0] = v.x; xr[i][1] = v.y; xr[i][2] = v.z; xr[i][3] = v.w;
        }
        #pragma unroll
        for (int j = 0; j < 4; j++) {
            const int k = k4 * 4 + j;
            // w pairs for this k: 8 floats = 4 f32x2, two 16B LDS
            const u64* wrow = (const u64*)&Ws[k * OUT_F + n0];
            u64 wp0 = wrow[0], wp1 = wrow[1], wp2 = wrow[2], wp3 = wrow[3];
            #pragma unroll
            for (int i = 0; i < 4; i++) {
                u64 xp;
                PACK2(xp, __float_as_uint(xr[i][j]));
                FMA2(acc[i][0], xp, wp0);
                FMA2(acc[i][1], xp, wp1);
                FMA2(acc[i][2], xp, wp2);
                FMA2(acc[i][3], xp, wp3);
            }
        }
    }

    // ---- bias + store
    const u64* bp = (const u64*)(bias + (size_t)h * OUT_F + n0);
    u64 b0 = bp[0], b1 = bp[1], b2 = bp[2], b3 = bp[3];

    #pragma unroll
    for (int i = 0; i < 4; i++) {
        const int node = g * NPG + m0 + i;
        u64 o0, o1, o2, o3;
        ADD2(o0, acc[i][0], b0);
        ADD2(o1, acc[i][1], b1);
        ADD2(o2, acc[i][2], b2);
        ADD2(o3, acc[i][3], b3);
        u64* dst = (u64*)&out[(size_t)node * OUT_F + n0];
        dst[0] = o0; dst[1] = o1; dst[2] = o2; dst[3] = o3;
    }
}

extern "C" void kernel_launch(void* const* d_in, const int* in_sizes, int n_in,
                              void* d_out, int out_size)
{
    const float* inputs = (const float*)d_in[0];
    // d_in[1] = n_node (fixed 64/graph per problem spec)
    const int*   head   = (const int*)d_in[2];
    const float* kern   = (const float*)d_in[3];
    const float* bias   = (const float*)d_in[4];
    float*       out    = (float*)d_out;

    const int n_graphs = in_sizes[2];            // 256
    const int smem_bytes = (IN_F * OUT_F + NPG * IN_F) * sizeof(float);  // 96 KB

    cudaFuncSetAttribute(mhl_kernel, cudaFuncAttributeMaxDynamicSharedMemorySize, smem_bytes);
    mhl_kernel<<<n_graphs, 256, smem_bytes>>>(inputs, head, kern, bias, out);
}

// round 3
// speedup vs baseline: 2.2414x; 2.2414x over previous
#include <cuda_runtime.h>
#include <cstdint>

typedef unsigned int u32;

#define NPG   64
#define IN_F  128
#define OUT_F 128
#define XS_STRIDE 132   // 128 + 4 pad: A-fragment LDS bank = 4*gid + tig = lane (conflict-free)

#define CVT_TF32(d, s) asm("cvt.rna.tf32.f32 %0, %1;" : "=r"(d) : "f"(s))

__device__ __forceinline__ void mma_tf32(float* c,
                                         u32 a0, u32 a1, u32 a2, u32 a3,
                                         u32 b0, u32 b1)
{
    asm volatile(
        "mma.sync.aligned.m16n8k8.row.col.f32.tf32.tf32.f32 "
        "{%0,%1,%2,%3}, {%4,%5,%6,%7}, {%8,%9}, {%0,%1,%2,%3};"
        : "+f"(c[0]), "+f"(c[1]), "+f"(c[2]), "+f"(c[3])
        : "r"(a0), "r"(a1), "r"(a2), "r"(a3), "r"(b0), "r"(b1));
}

__global__ void __launch_bounds__(128)
mhl_mma_kernel(const float* __restrict__ x,
               const int*   __restrict__ head,
               const float* __restrict__ kern,
               const float* __restrict__ bias,
               float*       __restrict__ out)
{
    __shared__ u32 Xs[NPG * XS_STRIDE];   // 33792 B, tf32-converted X tile

    const int tid  = threadIdx.x;
    const int wid  = tid >> 5;
    const int lane = tid & 31;
    const int gid  = lane >> 2;           // group id (0..7)
    const int tig  = lane & 3;            // thread in group (0..3)
    const int g    = blockIdx.x;
    const int h    = head[g];

    // ---- stage X[64][128] -> smem as tf32, padded stride ----
    {
        const float4* Xg = (const float4*)(x + (size_t)g * NPG * IN_F);
        #pragma unroll
        for (int it = 0; it < 16; it++) {
            const int idx  = tid + it * 128;      // 2048 float4 chunks
            const int node = idx >> 5;
            const int c4   = idx & 31;            // float4 index within row
            float4 v = Xg[idx];
            u32 r0, r1, r2, r3;
            CVT_TF32(r0, v.x); CVT_TF32(r1, v.y);
            CVT_TF32(r2, v.z); CVT_TF32(r3, v.w);
            u32* dst = &Xs[node * XS_STRIDE + c4 * 4];
            dst[0] = r0; dst[1] = r1; dst[2] = r2; dst[3] = r3;
        }
    }
    __syncthreads();

    // ---- mainloop: A from smem, B straight from global (L2-hot, no transpose) ----
    float acc[4][4][4];
    #pragma unroll
    for (int i = 0; i < 4; i++)
        #pragma unroll
        for (int j = 0; j < 4; j++)
            #pragma unroll
            for (int r = 0; r < 4; r++)
                acc[i][j][r] = 0.0f;

    // B element (k, n) at kern[h*16384 + k*128 + n]; this warp: n = wid*32 + 8j + gid
    const float* pW = kern + (size_t)h * IN_F * OUT_F + tig * OUT_F + wid * 32 + gid;
    const u32*   pX = Xs + gid * XS_STRIDE + tig;

    #pragma unroll
    for (int s = 0; s < 16; s++) {
        // B fragments for 4 n-tiles: b0 at k=8s+tig, b1 at k=8s+tig+4
        u32 b0[4], b1[4];
        #pragma unroll
        for (int j = 0; j < 4; j++) {
            float w0 = __ldg(pW + s * 8 * OUT_F + j * 8);
            float w1 = __ldg(pW + (s * 8 + 4) * OUT_F + j * 8);
            CVT_TF32(b0[j], w0);
            CVT_TF32(b1[j], w1);
        }
        // A fragments per m-tile, then 4 mma each
        #pragma unroll
        for (int i = 0; i < 4; i++) {
            const u32* pa = pX + i * 16 * XS_STRIDE + s * 8;
            u32 a0 = pa[0];
            u32 a1 = pa[8 * XS_STRIDE];
            u32 a2 = pa[4];
            u32 a3 = pa[8 * XS_STRIDE + 4];
            #pragma unroll
            for (int j = 0; j < 4; j++)
                mma_tf32(acc[i][j], a0, a1, a2, a3, b0[j], b1[j]);
        }
    }

    // ---- epilogue: bias + coalesced (32B-sector) float2 stores ----
    float bb[4][2];
    #pragma unroll
    for (int j = 0; j < 4; j++) {
        const int col = wid * 32 + 8 * j + 2 * tig;
        bb[j][0] = __ldg(bias + (size_t)h * OUT_F + col);
        bb[j][1] = __ldg(bias + (size_t)h * OUT_F + col + 1);
    }

    #pragma unroll
    for (int i = 0; i < 4; i++) {
        const int node0 = g * NPG + 16 * i + gid;
        #pragma unroll
        for (int j = 0; j < 4; j++) {
            const int col = wid * 32 + 8 * j + 2 * tig;
            float2 v0 = make_float2(acc[i][j][0] + bb[j][0], acc[i][j][1] + bb[j][1]);
            float2 v1 = make_float2(acc[i][j][2] + bb[j][0], acc[i][j][3] + bb[j][1]);
            *(float2*)&out[(size_t)node0 * OUT_F + col]       = v0;
            *(float2*)&out[(size_t)(node0 + 8) * OUT_F + col] = v1;
        }
    }
}

extern "C" void kernel_launch(void* const* d_in, const int* in_sizes, int n_in,
                              void* d_out, int out_size)
{
    const float* inputs = (const float*)d_in[0];
    const int*   head   = (const int*)d_in[2];
    const float* kern   = (const float*)d_in[3];
    const float* bias   = (const float*)d_in[4];
    float*       out    = (float*)d_out;
    const int n_graphs  = in_sizes[2];   // 256

    mhl_mma_kernel<<<n_graphs, 128>>>(inputs, head, kern, bias, out);
}

// round 4
// speedup vs baseline: 2.2750x; 1.0150x over previous
#include <cuda_runtime.h>
#include <cstdint>

typedef unsigned int u32;

#define NPG   64
#define IN_F  128
#define OUT_F 128
#define XS_STRIDE 132   // 128 + 4 pad: A-fragment LDS bank = 4*gid + tig (+s*8) = distinct per lane

#define CVT_TF32(d, s) asm("cvt.rna.tf32.f32 %0, %1;" : "=r"(d) : "f"(s))

__device__ __forceinline__ void mma_tf32(float* c,
                                         u32 a0, u32 a1, u32 a2, u32 a3,
                                         u32 b0, u32 b1)
{
    asm volatile(
        "mma.sync.aligned.m16n8k8.row.col.f32.tf32.tf32.f32 "
        "{%0,%1,%2,%3}, {%4,%5,%6,%7}, {%8,%9}, {%0,%1,%2,%3};"
        : "+f"(c[0]), "+f"(c[1]), "+f"(c[2]), "+f"(c[3])
        : "r"(a0), "r"(a1), "r"(a2), "r"(a3), "r"(b0), "r"(b1));
}

__global__ void __launch_bounds__(256)
mhl_mma_kernel(const float* __restrict__ x,
               const int*   __restrict__ head,
               const float* __restrict__ kern,
               const float* __restrict__ bias,
               float*       __restrict__ out)
{
    __shared__ u32 Xs[NPG * XS_STRIDE];   // 33792 B, tf32-converted X tile

    const int tid  = threadIdx.x;
    const int wid  = tid >> 5;            // 0..7, owns n-slice of 16
    const int lane = tid & 31;
    const int gid  = lane >> 2;           // group id (0..7)
    const int tig  = lane & 3;            // thread in group (0..3)
    const int g    = blockIdx.x;
    const int h    = head[g];
    const int n0   = wid * 16;

    // ---- stage X[64][128] -> smem as tf32, padded stride ----
    {
        const float4* Xg = (const float4*)(x + (size_t)g * NPG * IN_F);
        #pragma unroll
        for (int it = 0; it < 8; it++) {
            const int idx  = tid + it * 256;      // 2048 float4 chunks
            const int node = idx >> 5;
            const int c4   = idx & 31;
            float4 v = Xg[idx];
            u32 r0, r1, r2, r3;
            CVT_TF32(r0, v.x); CVT_TF32(r1, v.y);
            CVT_TF32(r2, v.z); CVT_TF32(r3, v.w);
            u32* dst = &Xs[node * XS_STRIDE + c4 * 4];
            dst[0] = r0; dst[1] = r1; dst[2] = r2; dst[3] = r3;
        }
    }
    __syncthreads();

    float acc[4][2][4];
    #pragma unroll
    for (int i = 0; i < 4; i++)
        #pragma unroll
        for (int j = 0; j < 2; j++)
            #pragma unroll
            for (int r = 0; r < 4; r++)
                acc[i][j][r] = 0.0f;

    // B element (k, n) at kern[h*16384 + k*128 + n]; this warp's n = n0 + 8j + gid
    const float* pW = kern + (size_t)h * IN_F * OUT_F + tig * OUT_F + n0 + gid;
    const u32*   pX = Xs + gid * XS_STRIDE + tig;

    // ---- software pipeline: prefetch next step's W while computing current ----
    float wn[2][2];                                   // [j][k-half]
    #pragma unroll
    for (int j = 0; j < 2; j++) {
        wn[j][0] = __ldg(pW + j * 8);                 // k = tig
        wn[j][1] = __ldg(pW + 4 * OUT_F + j * 8);     // k = tig + 4
    }

    #pragma unroll
    for (int s = 0; s < 16; s++) {
        // current B fragments
        u32 b0[2], b1[2];
        #pragma unroll
        for (int j = 0; j < 2; j++) {
            CVT_TF32(b0[j], wn[j][0]);
            CVT_TF32(b1[j], wn[j][1]);
        }
        // prefetch next step
        if (s < 15) {
            const float* pWn = pW + (s + 1) * 8 * OUT_F;
            #pragma unroll
            for (int j = 0; j < 2; j++) {
                wn[j][0] = __ldg(pWn + j * 8);
                wn[j][1] = __ldg(pWn + 4 * OUT_F + j * 8);
            }
        }
        // A fragments per m-tile, 2 mma each
        #pragma unroll
        for (int i = 0; i < 4; i++) {
            const u32* pa = pX + i * 16 * XS_STRIDE + s * 8;
            u32 a0 = pa[0];
            u32 a1 = pa[8 * XS_STRIDE];
            u32 a2 = pa[4];
            u32 a3 = pa[8 * XS_STRIDE + 4];
            mma_tf32(acc[i][0], a0, a1, a2, a3, b0[0], b1[0]);
            mma_tf32(acc[i][1], a0, a1, a2, a3, b0[1], b1[1]);
        }
    }

    // ---- epilogue: bias + coalesced float2 stores ----
    float bb[2][2];
    #pragma unroll
    for (int j = 0; j < 2; j++) {
        const int col = n0 + 8 * j + 2 * tig;
        bb[j][0] = __ldg(bias + (size_t)h * OUT_F + col);
        bb[j][1] = __ldg(bias + (size_t)h * OUT_F + col + 1);
    }

    #pragma unroll
    for (int i = 0; i < 4; i++) {
        const int node0 = g * NPG + 16 * i + gid;
        #pragma unroll
        for (int j = 0; j < 2; j++) {
            const int col = n0 + 8 * j + 2 * tig;
            float2 v0 = make_float2(acc[i][j][0] + bb[j][0], acc[i][j][1] + bb[j][1]);
            float2 v1 = make_float2(acc[i][j][2] + bb[j][0], acc[i][j][3] + bb[j][1]);
            *(float2*)&out[(size_t)node0 * OUT_F + col]       = v0;
            *(float2*)&out[(size_t)(node0 + 8) * OUT_F + col] = v1;
        }
    }
}

extern "C" void kernel_launch(void* const* d_in, const int* in_sizes, int n_in,
                              void* d_out, int out_size)
{
    const float* inputs = (const float*)d_in[0];
    const int*   head   = (const int*)d_in[2];
    const float* kern   = (const float*)d_in[3];
    const float* bias   = (const float*)d_in[4];
    float*       out    = (float*)d_out;
    const int n_graphs  = in_sizes[2];   // 256

    mhl_mma_kernel<<<n_graphs, 256>>>(inputs, head, kern, bias, out);
}